// round 1
// baseline (speedup 1.0000x reference)
#include <cuda_runtime.h>
#include <cuda_bf16.h>
#include <cstdint>

// Problem constants (fixed by the reference)
#define B_    4
#define C_    512
#define H_    64
#define W_    208
#define HID_  512
#define DS_   16
#define NREG_ 4

// Scratch (device globals; no allocation allowed)
__device__ float g_delta[B_ * NREG_ * C_];   // delta[b, r, c]
__device__ int   g_perm[B_ * W_];            // output col w  -> source col
__device__ int   g_reg [B_ * W_];            // output col w  -> region id (0..3)

// ---------------------------------------------------------------------------
// Kernel 1: delta[b,r,c] = (text_feat[r,b,:] @ Wv[r]) @ Wo[r]
// One block per (b, r). 16 blocks, 256 threads.
// text_feat: (NREG, B, HID), Wv: (NREG, HID, HID), Wo: (NREG, HID, C)
// ---------------------------------------------------------------------------
__global__ void compute_delta_kernel(const float* __restrict__ text_feat,
                                     const float* __restrict__ Wv,
                                     const float* __restrict__ Wo) {
    __shared__ float s_tf[HID_];
    __shared__ float s_tmp[HID_];

    const int b = blockIdx.x / NREG_;
    const int r = blockIdx.x % NREG_;
    const int tid = threadIdx.x;

    // load text_feat[r, b, :]
    for (int h = tid; h < HID_; h += blockDim.x)
        s_tf[h] = text_feat[(r * B_ + b) * HID_ + h];
    __syncthreads();

    // tmp[d] = sum_h tf[h] * Wv[r, h, d]   (coalesced over d)
    const float* wv = Wv + (size_t)r * HID_ * HID_;
    for (int d = tid; d < HID_; d += blockDim.x) {
        float acc = 0.f;
        #pragma unroll 8
        for (int h = 0; h < HID_; ++h)
            acc = fmaf(s_tf[h], wv[(size_t)h * HID_ + d], acc);
        s_tmp[d] = acc;
    }
    __syncthreads();

    // delta[b, r, c] = sum_d tmp[d] * Wo[r, d, c]   (coalesced over c)
    const float* wo = Wo + (size_t)r * HID_ * C_;
    for (int c = tid; c < C_; c += blockDim.x) {
        float acc = 0.f;
        #pragma unroll 8
        for (int d = 0; d < HID_; ++d)
            acc = fmaf(s_tmp[d], wo[(size_t)d * C_ + c], acc);
        g_delta[(b * NREG_ + r) * C_ + c] = acc;
    }
}

// ---------------------------------------------------------------------------
// Kernel 2: stable counting sort of col_labels[b, :] (values 1..4).
// col_labels[b, w] = text_mask[b, 0, 0, w*DS]  (row 0 of strided downsample).
// perm[b, pos] = w, reg[b, pos] = label-1  (pos assigned ascending-w within
// each label bucket -> matches jnp.argsort stable).
// One block per batch; parallel label load, serial (trivial) sort by thread 0.
// ---------------------------------------------------------------------------
__global__ void compute_perm_kernel(const int* __restrict__ text_mask) {
    __shared__ int s_lab[W_];
    const int b = blockIdx.x;
    const size_t mask_batch_stride = (size_t)(H_ * DS_) * (W_ * DS_);

    for (int w = threadIdx.x; w < W_; w += blockDim.x)
        s_lab[w] = text_mask[b * mask_batch_stride + (size_t)w * DS_];
    __syncthreads();

    if (threadIdx.x == 0) {
        int count[NREG_ + 1] = {0, 0, 0, 0, 0};
        for (int w = 0; w < W_; ++w) count[s_lab[w]]++;
        int start[NREG_ + 1];
        start[1] = 0;
        for (int l = 2; l <= NREG_; ++l) start[l] = start[l - 1] + count[l - 1];
        for (int w = 0; w < W_; ++w) {
            const int l = s_lab[w];
            const int pos = start[l]++;
            g_perm[b * W_ + pos] = w;
            g_reg [b * W_ + pos] = l - 1;
        }
    }
}

// ---------------------------------------------------------------------------
// Kernel 3: out[b,c,h,w] = image[b,c,h, perm[b,w]] + delta[b, reg[b,w], c]
// Grid-stride over float4 output elements. W=208 -> 52 float4 per row.
// Writes perfectly coalesced; reads gathered only within each 832B row (L1
// absorbs); delta/perm LUTs L2/L1-resident & nearly warp-uniform.
// ---------------------------------------------------------------------------
#define ROW4_ (W_ / 4)           // 52
#define TOTAL4_ (B_ * C_ * H_ * ROW4_)

__global__ __launch_bounds__(256) void gather_add_kernel(
        const float* __restrict__ image, float* __restrict__ out) {
    int idx = blockIdx.x * blockDim.x + threadIdx.x;
    if (idx >= TOTAL4_) return;

    const int w4  = idx % ROW4_;
    const int row = idx / ROW4_;              // linear over (b, c, h)
    const int c   = (row / H_) % C_;
    const int b   = row / (H_ * C_);
    const int w   = w4 * 4;

    const int4 s4 = *reinterpret_cast<const int4*>(&g_perm[b * W_ + w]);
    const int4 r4 = *reinterpret_cast<const int4*>(&g_reg [b * W_ + w]);

    const float* imrow = image + (size_t)row * W_;
    const float* drow  = &g_delta[b * NREG_ * C_ + c];  // + r*C_

    float4 o;
    o.x = __ldg(imrow + s4.x) + drow[r4.x * C_];
    o.y = __ldg(imrow + s4.y) + drow[r4.y * C_];
    o.z = __ldg(imrow + s4.z) + drow[r4.z * C_];
    o.w = __ldg(imrow + s4.w) + drow[r4.w * C_];

    reinterpret_cast<float4*>(out)[idx] = o;
}

// ---------------------------------------------------------------------------
// Launch. Input order (metadata): image_feature f32, text_feat f32,
// text_mask i32, Wq f32 (unused), Wk f32 (unused), Wv f32, Wo f32.
// Output: f32, B*C*H*W.
// ---------------------------------------------------------------------------
extern "C" void kernel_launch(void* const* d_in, const int* in_sizes, int n_in,
                              void* d_out, int out_size) {
    const float* image     = (const float*)d_in[0];
    const float* text_feat = (const float*)d_in[1];
    const int*   text_mask = (const int*)  d_in[2];
    const float* Wv        = (const float*)d_in[5];
    const float* Wo        = (const float*)d_in[6];
    float* out = (float*)d_out;

    compute_delta_kernel<<<B_ * NREG_, 256>>>(text_feat, Wv, Wo);
    compute_perm_kernel<<<B_, 64>>>(text_mask);

    const int threads = 256;
    const int blocks = (TOTAL4_ + threads - 1) / threads;
    gather_add_kernel<<<blocks, threads>>>(image, out);
}

// round 3
// speedup vs baseline: 2.6922x; 2.6922x over previous
#include <cuda_runtime.h>
#include <cuda_bf16.h>
#include <cstdint>

// Problem constants (fixed by the reference)
#define B_    4
#define C_    512
#define H_    64
#define W_    208
#define HID_  512
#define DS_   16
#define NREG_ 4

#define DT_   16   // d-tiles of 32 (one 128B sector)
#define CT_   16   // c-tiles of 32
#define SG_   16   // reduction subgroups per block (512 threads)

// Scratch (device globals; no allocation allowed)
__device__ float g_tmp  [NREG_ * B_ * HID_];  // tmp[r, b, d]
__device__ float g_delta[B_ * NREG_ * C_];    // delta[b, r, c]
__device__ int   g_perm[B_ * W_];             // output col w -> source col
__device__ int   g_reg [B_ * W_];             // output col w -> region id (0..3)

// ---------------------------------------------------------------------------
// Stage 1: tmp[r,b,d] = sum_h tf[r,b,h] * Wv[r,h,d]
// grid = NREG * DT_ (64 blocks), 512 threads = 16 h-subgroups x 32 d-lanes.
// Each block streams Wv[r, :, dtile] (512 rows x one 128B sector); all 4
// batches accumulated per thread so Wv is read exactly once.
// ---------------------------------------------------------------------------
__global__ __launch_bounds__(512) void delta_stage1(
        const float* __restrict__ text_feat, const float* __restrict__ Wv) {
    const int r  = blockIdx.x / DT_;
    const int dt = blockIdx.x % DT_;
    const int dl = threadIdx.x & 31;   // d lane within tile
    const int hs = threadIdx.x >> 5;   // h subgroup 0..15
    const int d  = dt * 32 + dl;

    __shared__ float s_tf[B_][HID_];   // 8 KB
    for (int i = threadIdx.x; i < B_ * HID_; i += 512)
        s_tf[i / HID_][i % HID_] = text_feat[(size_t)r * B_ * HID_ + i];
    __syncthreads();

    const float* wv = Wv + (size_t)r * HID_ * HID_ + d;
    float acc[B_] = {0.f, 0.f, 0.f, 0.f};
    #pragma unroll 16
    for (int h = hs; h < HID_; h += SG_) {
        const float w = wv[(size_t)h * HID_];
        #pragma unroll
        for (int b = 0; b < B_; ++b)
            acc[b] = fmaf(s_tf[b][h], w, acc[b]);
    }

    __shared__ float s_red[SG_][B_][32];
    #pragma unroll
    for (int b = 0; b < B_; ++b) s_red[hs][b][dl] = acc[b];
    __syncthreads();

    if (hs == 0) {
        #pragma unroll
        for (int b = 0; b < B_; ++b) {
            float s = 0.f;
            #pragma unroll
            for (int g = 0; g < SG_; ++g) s += s_red[g][b][dl];
            g_tmp[((size_t)r * B_ + b) * HID_ + d] = s;
        }
    }
}

// ---------------------------------------------------------------------------
// Stage 2: delta[b,r,c] = sum_d tmp[r,b,d] * Wo[r,d,c]
// Same structure against Wo (4 MB read once, 64 blocks x 512 threads).
// ---------------------------------------------------------------------------
__global__ __launch_bounds__(512) void delta_stage2(
        const float* __restrict__ Wo) {
    const int r  = blockIdx.x / CT_;
    const int ct = blockIdx.x % CT_;
    const int cl = threadIdx.x & 31;
    const int ds = threadIdx.x >> 5;   // d subgroup 0..15
    const int c  = ct * 32 + cl;

    __shared__ float s_tmp[B_][HID_];
    for (int i = threadIdx.x; i < B_ * HID_; i += 512)
        s_tmp[i / HID_][i % HID_] = g_tmp[(size_t)r * B_ * HID_ + i];
    __syncthreads();

    const float* wo = Wo + (size_t)r * HID_ * C_ + c;
    float acc[B_] = {0.f, 0.f, 0.f, 0.f};
    #pragma unroll 16
    for (int d = ds; d < HID_; d += SG_) {
        const float w = wo[(size_t)d * C_];
        #pragma unroll
        for (int b = 0; b < B_; ++b)
            acc[b] = fmaf(s_tmp[b][d], w, acc[b]);
    }

    __shared__ float s_red[SG_][B_][32];
    #pragma unroll
    for (int b = 0; b < B_; ++b) s_red[ds][b][cl] = acc[b];
    __syncthreads();

    if (ds == 0) {
        #pragma unroll
        for (int b = 0; b < B_; ++b) {
            float s = 0.f;
            #pragma unroll
            for (int g = 0; g < SG_; ++g) s += s_red[g][b][cl];
            g_delta[((size_t)b * NREG_ + r) * C_ + c] = s;
        }
    }
}

// ---------------------------------------------------------------------------
// Perm: stable counting sort of col_labels[b,:] (values 1..4).
// col_labels[b, w] = text_mask[b, 0, 0, w*DS].
// ---------------------------------------------------------------------------
__global__ void compute_perm_kernel(const int* __restrict__ text_mask) {
    __shared__ int s_lab[W_];
    const int b = blockIdx.x;
    const size_t mask_batch_stride = (size_t)(H_ * DS_) * (W_ * DS_);

    for (int w = threadIdx.x; w < W_; w += blockDim.x)
        s_lab[w] = text_mask[b * mask_batch_stride + (size_t)w * DS_];
    __syncthreads();

    if (threadIdx.x == 0) {
        int count[NREG_ + 1] = {0, 0, 0, 0, 0};
        for (int w = 0; w < W_; ++w) count[s_lab[w]]++;
        int start[NREG_ + 1];
        start[1] = 0;
        for (int l = 2; l <= NREG_; ++l) start[l] = start[l - 1] + count[l - 1];
        for (int w = 0; w < W_; ++w) {
            const int l = s_lab[w];
            const int pos = start[l]++;
            g_perm[b * W_ + pos] = w;
            g_reg [b * W_ + pos] = l - 1;
        }
    }
}

// ---------------------------------------------------------------------------
// Gather: out[b,c,h,w] = image[b,c,h, perm[b,w]] + delta[b, reg[b,w], c]
// Grid-stride over float4 outputs. Writes coalesced; reads permuted within
// each 832B row (L1 absorbs); LUTs L2-resident and ~warp-uniform.
// ---------------------------------------------------------------------------
#define ROW4_ (W_ / 4)                 // 52
#define TOTAL4_ (B_ * C_ * H_ * ROW4_)

__global__ __launch_bounds__(256) void gather_add_kernel(
        const float* __restrict__ image, float* __restrict__ out) {
    int idx = blockIdx.x * blockDim.x + threadIdx.x;
    if (idx >= TOTAL4_) return;

    const int w4  = idx % ROW4_;
    const int row = idx / ROW4_;       // linear over (b, c, h)
    const int c   = (row / H_) % C_;
    const int b   = row / (H_ * C_);
    const int w   = w4 * 4;

    const int4 s4 = *reinterpret_cast<const int4*>(&g_perm[b * W_ + w]);
    const int4 r4 = *reinterpret_cast<const int4*>(&g_reg [b * W_ + w]);

    const float* imrow = image + (size_t)row * W_;
    const float* drow  = &g_delta[b * NREG_ * C_ + c];  // + r*C_

    float4 o;
    o.x = __ldg(imrow + s4.x) + drow[r4.x * C_];
    o.y = __ldg(imrow + s4.y) + drow[r4.y * C_];
    o.z = __ldg(imrow + s4.z) + drow[r4.z * C_];
    o.w = __ldg(imrow + s4.w) + drow[r4.w * C_];

    reinterpret_cast<float4*>(out)[idx] = o;
}

// ---------------------------------------------------------------------------
// Launch. Input order (metadata): image_feature f32, text_feat f32,
// text_mask i32, Wq f32 (unused), Wk f32 (unused), Wv f32, Wo f32.
// ---------------------------------------------------------------------------
extern "C" void kernel_launch(void* const* d_in, const int* in_sizes, int n_in,
                              void* d_out, int out_size) {
    const float* image     = (const float*)d_in[0];
    const float* text_feat = (const float*)d_in[1];
    const int*   text_mask = (const int*)  d_in[2];
    const float* Wv        = (const float*)d_in[5];
    const float* Wo        = (const float*)d_in[6];
    float* out = (float*)d_out;

    delta_stage1<<<NREG_ * DT_, 512>>>(text_feat, Wv);
    compute_perm_kernel<<<B_, 64>>>(text_mask);
    delta_stage2<<<NREG_ * CT_, 512>>>(Wo);

    const int threads = 256;
    const int blocks = (TOTAL4_ + threads - 1) / threads;
    gather_add_kernel<<<blocks, threads>>>(image, out);
}